// round 13
// baseline (speedup 1.0000x reference)
#include <cuda_runtime.h>
#include <cstdint>

#define EDGES 625000
#define DD    128
#define BE    128
#define NT    512
#define NCTA  ((EDGES + BE - 1) / BE)   // 4883

// ---------------- smem layout (bytes) ----------------
// A chunk (k64, fp16 natural+swizzle): 128 rows x 128B = 16384 ; x2
// H (fp16 natural+swizzle): 128 rows x 256B = 32768
#define SM_A0   0
#define SM_A1   16384
#define SM_H    32768
#define SM_PART 65536          // 128 rows x 4 x float2 = 4096
#define SM_P    69632
#define P_B1    (SM_P + 0)
#define P_B2    (SM_P + 512)
#define P_G     (SM_P + 1024)
#define P_BT    (SM_P + 1536)
#define P_SEND  (SM_P + 2048)
#define P_RECV  (SM_P + 2560)
#define SMEM_ALLOC 73728

// weights in fp16 m16n8k16 B-fragment layout (verified R6/R7):
// block(kstep16, ntile8) = 256B: uint32 slot = lane*2 + r ; lane=(g<<2)|t
//   slot lo/hi = W[k][n], W[k+1][n]  with k = ks*16 + r*8 + t*2 , n = nt*8 + g
__device__ __align__(16) uint32_t g_W1F[24 * 16 * 64];
__device__ __align__(16) uint32_t g_W2F[8 * 16 * 64];

__device__ __forceinline__ uint32_t packf16(float lo, float hi) {
    uint32_t u;
    asm("cvt.rn.f16x2.f32 %0, %1, %2;" : "=r"(u) : "f"(hi), "f"(lo));
    return u;
}

__global__ void prep_w_kernel(const float* __restrict__ W1,
                              const float* __restrict__ W2) {
    int i = blockIdx.x * 256 + threadIdx.x;
    if (i < 24 * 16 * 64) {
        int blk = i >> 6, w = i & 63;
        int lane = w >> 1, r = w & 1;
        int g = lane >> 2, t = lane & 3;
        int ks = blk >> 4, nt = blk & 15;
        int k = ks * 16 + r * 8 + t * 2;
        int n = nt * 8 + g;
        g_W1F[i] = packf16(W1[k * 128 + n], W1[(k + 1) * 128 + n]);
    }
    if (i < 8 * 16 * 64) {
        int blk = i >> 6, w = i & 63;
        int lane = w >> 1, r = w & 1;
        int g = lane >> 2, t = lane & 3;
        int ks = blk >> 4, nt = blk & 15;
        int k = ks * 16 + r * 8 + t * 2;
        int n = nt * 8 + g;
        g_W2F[i] = packf16(W2[k * 128 + n], W2[(k + 1) * 128 + n]);
    }
}

__device__ __forceinline__ void mma_fp16(float& c0, float& c1, float& c2, float& c3,
                                         uint32_t a0, uint32_t a1, uint32_t a2, uint32_t a3,
                                         uint32_t b0, uint32_t b1) {
    asm volatile("mma.sync.aligned.m16n8k16.row.col.f32.f16.f16.f32 "
                 "{%0,%1,%2,%3}, {%4,%5,%6,%7}, {%8,%9}, {%0,%1,%2,%3};"
                 : "+f"(c0), "+f"(c1), "+f"(c2), "+f"(c3)
                 : "r"(a0), "r"(a1), "r"(a2), "r"(a3), "r"(b0), "r"(b1));
}

__device__ __forceinline__ void ldsm4(uint32_t& r0, uint32_t& r1, uint32_t& r2, uint32_t& r3,
                                      uint32_t addr) {
    asm volatile("ldmatrix.sync.aligned.m8n8.x4.shared.b16 {%0,%1,%2,%3}, [%4];"
                 : "=r"(r0), "=r"(r1), "=r"(r2), "=r"(r3) : "r"(addr));
}

// per-half named barrier: id 1+h, 256 threads
#define HBAR(h) asm volatile("bar.sync %0, 256;" :: "r"(1 + (h)) : "memory")

__global__ __launch_bounds__(NT, 1) void edge_mlp_mma(
    const float* __restrict__ node_attr,
    const void*  __restrict__ eidx_raw,
    const float* __restrict__ edge_attr,
    const float* __restrict__ b1g,
    const float* __restrict__ b2g,
    const float* __restrict__ gg,
    const float* __restrict__ btg,
    float* __restrict__ out)
{
    extern __shared__ char smem[];
    uint32_t smb;
    asm("{ .reg .u64 t; cvta.to.shared.u64 t, %1; cvt.u32.u64 %0, t; }"
        : "=r"(smb) : "l"(smem));

    const int tid   = threadIdx.x;
    const int wid   = tid >> 5;
    const int lane  = tid & 31;
    const int g     = lane >> 2;
    const int t     = lane & 3;
    const int wm    = wid >> 2;    // 0..3 (M quarter, 32 rows); halves: wm{0,1} | wm{2,3}
    const int wn    = wid & 3;     // 0..3 (N quarter, 32 cols)
    const int h     = tid >> 8;    // half id
    const int ht    = tid & 255;   // thread-in-half
    const int e0    = blockIdx.x * BE;
    const int lrow7 = lane & 7;
    const int rowb  = wm * 32 + lrow7 + 8 * ((lane >> 3) & 1);
    const int grx   = (lane >> 4) & 1;

    // B fragment base slot for this warp: + blk*64 ; blk = ks*16 + wn*4 + j
    const uint32_t* w1p = g_W1F + (wn * 4) * 64 + lane * 2;
    const uint32_t* w2p = g_W2F + (wn * 4) * 64 + lane * 2;

    // ---- prefetch B chunk 0 (GEMM1 ksteps 0..3) straight into registers ----
    uint2 prB[16];
    #pragma unroll
    for (int s = 0; s < 4; s++)
        #pragma unroll
        for (int j = 0; j < 4; j++)
            prB[s * 4 + j] = *(const uint2*)(w1p + (s * 16 + j) * 64);

    if (tid < 128) {
        ((float*)(smem + P_B1))[tid] = b1g[tid];
        ((float*)(smem + P_B2))[tid] = b2g[tid];
        ((float*)(smem + P_G ))[tid] = gg[tid];
        ((float*)(smem + P_BT))[tid] = btg[tid];
    }
    const int* raw32 = (const int*)eidx_raw;
    bool is64 = true;
    #pragma unroll
    for (int i = 0; i < 16; i++) is64 &= (raw32[2 * i + 1] == 0);
    if (tid < BE) {
        int eg = e0 + tid; if (eg >= EDGES) eg = EDGES - 1;
        int s, r;
        if (is64) { const long long* p = (const long long*)eidx_raw;
                    s = (int)p[eg]; r = (int)p[EDGES + eg]; }
        else      { s = raw32[eg]; r = raw32[EDGES + eg]; }
        ((int*)(smem + P_SEND))[tid] = s;
        ((int*)(smem + P_RECV))[tid] = r;
    }
    __syncthreads();   // send/recv + params visible (only full barrier)

    const int* sSend = (const int*)(smem + P_SEND);
    const int* sRecv = (const int*)(smem + P_RECV);

    // prefetch A chunk 0 (sender, k 0..63): half-local 1024 float4 slots
    float4 prA[4];
    #pragma unroll
    for (int it = 0; it < 4; it++) {
        int idx = ht + it * 256;
        int row = h * 64 + (idx >> 4), jc = idx & 15;
        prA[it] = *(const float4*)(node_attr + (size_t)sSend[row] * DD + jc * 4);
    }

    float acc[2][4][4];
    #pragma unroll
    for (int i = 0; i < 2; i++)
        #pragma unroll
        for (int j = 0; j < 4; j++)
            #pragma unroll
            for (int r = 0; r < 4; r++) acc[i][j][r] = 0.0f;

    // =================== GEMM1: 6 chunks of k=64, B in registers ===================
    #pragma unroll 1
    for (int c = 0; c < 6; c++) {
        const uint32_t aoff = (c & 1) ? SM_A1 : SM_A0;
        char* abuf = smem + aoff;
        // scatter A(c): own half's rows, natural fp16 + XOR swizzle
        #pragma unroll
        for (int it = 0; it < 4; it++) {
            int idx = ht + it * 256;
            int row = h * 64 + (idx >> 4), jc = idx & 15;
            int sw = (jc >> 1) ^ (row & 7);
            uint2 v;
            v.x = packf16(prA[it].x, prA[it].y);
            v.y = packf16(prA[it].z, prA[it].w);
            *(uint2*)(abuf + row * 128 + sw * 16 + (jc & 1) * 8) = v;
        }
        HBAR(h);         // half's A(c) visible; half's MMA(c-1) done

        if (c < 5) {     // prefetch A(c+1)
            int cn = c + 1;
            #pragma unroll
            for (int it = 0; it < 4; it++) {
                int idx = ht + it * 256;
                int row = h * 64 + (idx >> 4), jc = idx & 15;
                const float* src;
                if (cn < 2)      src = node_attr + (size_t)sSend[row] * DD + cn * 64;
                else if (cn < 4) src = node_attr + (size_t)sRecv[row] * DD + (cn - 2) * 64;
                else { int eg = e0 + row; if (eg >= EDGES) eg = EDGES - 1;
                       src = edge_attr + (size_t)eg * DD + (cn - 4) * 64; }
                prA[it] = *(const float4*)(src + jc * 4);
            }
        }

        const uint32_t abase = smb + aoff;
        #pragma unroll
        for (int s = 0; s < 4; s++) {
            uint2 b[4];
            #pragma unroll
            for (int j = 0; j < 4; j++) b[j] = prB[s * 4 + j];
            // refill this s-slice for the next chunk (W1 chunks 1..5, then W2 chunk 0)
            if (c < 5) {
                #pragma unroll
                for (int j = 0; j < 4; j++)
                    prB[s * 4 + j] = *(const uint2*)(w1p + (((c + 1) * 4 + s) * 16 + j) * 64);
            } else {
                #pragma unroll
                for (int j = 0; j < 4; j++)
                    prB[s * 4 + j] = *(const uint2*)(w2p + (s * 16 + j) * 64);
            }
            #pragma unroll
            for (int i = 0; i < 2; i++) {
                uint32_t a0, a1, a2, a3;
                uint32_t ad = abase + (rowb + i * 16) * 128 +
                              (((s * 2 + grx) ^ lrow7) << 4);
                ldsm4(a0, a1, a2, a3, ad);
                #pragma unroll
                for (int j = 0; j < 4; j++)
                    mma_fp16(acc[i][j][0], acc[i][j][1], acc[i][j][2], acc[i][j][3],
                             a0, a1, a2, a3, b[j].x, b[j].y);
            }
        }
    }

    // ========== epilogue1: bias + ReLU -> H (own half rows) ==========
    {
        const float* B1 = (const float*)(smem + P_B1);
        #pragma unroll
        for (int i = 0; i < 2; i++) {
            int row_lo = wm * 32 + i * 16 + g;
            #pragma unroll
            for (int j = 0; j < 4; j++) {
                int col = wn * 32 + j * 8 + 2 * t;
                float x0 = fmaxf(acc[i][j][0] + B1[col],     0.0f);
                float x1 = fmaxf(acc[i][j][1] + B1[col + 1], 0.0f);
                float x2 = fmaxf(acc[i][j][2] + B1[col],     0.0f);
                float x3 = fmaxf(acc[i][j][3] + B1[col + 1], 0.0f);
                int swg = ((wn * 4 + j) ^ g) * 16 + 4 * t;
                *(uint32_t*)(smem + SM_H + row_lo * 256 + swg)       = packf16(x0, x1);
                *(uint32_t*)(smem + SM_H + (row_lo + 8) * 256 + swg) = packf16(x2, x3);
                acc[i][j][0] = 0.0f; acc[i][j][1] = 0.0f;
                acc[i][j][2] = 0.0f; acc[i][j][3] = 0.0f;
            }
        }
    }
    HBAR(h);           // half's H rows visible

    // ====== GEMM2: 2 chunks of k=64, A via LDSM from H, B in registers ======
    #pragma unroll 1
    for (int c = 0; c < 2; c++) {
        #pragma unroll
        for (int s = 0; s < 4; s++) {
            uint2 b[4];
            #pragma unroll
            for (int j = 0; j < 4; j++) b[j] = prB[s * 4 + j];
            if (c == 0) {    // refill for GEMM2 chunk 1
                #pragma unroll
                for (int j = 0; j < 4; j++)
                    prB[s * 4 + j] = *(const uint2*)(w2p + ((4 + s) * 16 + j) * 64);
            }
            #pragma unroll
            for (int i = 0; i < 2; i++) {
                uint32_t a0, a1, a2, a3;
                uint32_t ad = smb + SM_H + (rowb + i * 16) * 256 +
                              (((c * 8 + s * 2 + grx) ^ lrow7) << 4);
                ldsm4(a0, a1, a2, a3, ad);
                #pragma unroll
                for (int j = 0; j < 4; j++)
                    mma_fp16(acc[i][j][0], acc[i][j][1], acc[i][j][2], acc[i][j][3],
                             a0, a1, a2, a3, b[j].x, b[j].y);
            }
        }
    }

    // ========== bias2 + LayerNorm from registers (own half rows) ==========
    {
        const float* B2 = (const float*)(smem + P_B2);
        #pragma unroll
        for (int i = 0; i < 2; i++)
            #pragma unroll
            for (int j = 0; j < 4; j++) {
                int col = wn * 32 + j * 8 + 2 * t;
                acc[i][j][0] += B2[col];     acc[i][j][1] += B2[col + 1];
                acc[i][j][2] += B2[col];     acc[i][j][3] += B2[col + 1];
            }
        float2* part = (float2*)(smem + SM_PART);   // [row][wn]
        #pragma unroll
        for (int i = 0; i < 2; i++)
            #pragma unroll
            for (int hi = 0; hi < 2; hi++) {
                float s = 0.0f, q = 0.0f;
                #pragma unroll
                for (int j = 0; j < 4; j++) {
                    float v0 = acc[i][j][hi * 2], v1 = acc[i][j][hi * 2 + 1];
                    s += v0 + v1; q += v0 * v0 + v1 * v1;
                }
                s += __shfl_xor_sync(0xffffffffu, s, 1);
                q += __shfl_xor_sync(0xffffffffu, q, 1);
                s += __shfl_xor_sync(0xffffffffu, s, 2);
                q += __shfl_xor_sync(0xffffffffu, q, 2);
                if (t == 0) {
                    int row = wm * 32 + i * 16 + g + 8 * hi;
                    part[row * 4 + wn] = make_float2(s, q);
                }
            }
    }
    HBAR(h);           // half's partials visible

    {
        const float* G  = (const float*)(smem + P_G);
        const float* Bt = (const float*)(smem + P_BT);
        const float2* part = (const float2*)(smem + SM_PART);
        #pragma unroll
        for (int i = 0; i < 2; i++)
            #pragma unroll
            for (int hi = 0; hi < 2; hi++) {
                int row = wm * 32 + i * 16 + g + 8 * hi;
                float2 p0 = part[row * 4 + 0], p1 = part[row * 4 + 1];
                float2 p2 = part[row * 4 + 2], p3 = part[row * 4 + 3];
                float sum = p0.x + p1.x + p2.x + p3.x;
                float sq  = p0.y + p1.y + p2.y + p3.y;
                float mu  = sum * (1.0f / 128.0f);
                float var = sq * (1.0f / 128.0f) - mu * mu;
                float rs  = rsqrtf(var + 1e-5f);
                int eg = e0 + row;
                if (eg < EDGES) {
                    float* o = out + (size_t)eg * DD;
                    #pragma unroll
                    for (int j = 0; j < 4; j++) {
                        int col = wn * 32 + j * 8 + 2 * t;
                        float2 v;
                        v.x = (acc[i][j][hi * 2]     - mu) * rs * G[col]     + Bt[col];
                        v.y = (acc[i][j][hi * 2 + 1] - mu) * rs * G[col + 1] + Bt[col + 1];
                        *(float2*)(o + col) = v;
                    }
                }
            }
    }
}

extern "C" void kernel_launch(void* const* d_in, const int* in_sizes, int n_in,
                              void* d_out, int out_size) {
    const float* node_attr = (const float*)d_in[0];
    const void*  eidx      = d_in[1];
    const float* edge_attr = (const float*)d_in[2];
    const float* W1        = (const float*)d_in[3];
    const float* b1        = (const float*)d_in[4];
    const float* W2        = (const float*)d_in[5];
    const float* b2        = (const float*)d_in[6];
    const float* gamma_    = (const float*)d_in[7];
    const float* beta_     = (const float*)d_in[8];

    cudaFuncSetAttribute(edge_mlp_mma, cudaFuncAttributeMaxDynamicSharedMemorySize, SMEM_ALLOC);

    prep_w_kernel<<<96, 256>>>(W1, W2);
    edge_mlp_mma<<<NCTA, NT, SMEM_ALLOC>>>(node_attr, eidx, edge_attr,
                                           b1, b2, gamma_, beta_, (float*)d_out);
}

// round 14
// speedup vs baseline: 1.0295x; 1.0295x over previous
#include <cuda_runtime.h>
#include <cstdint>

#define EDGES 625000
#define DD    128
#define BE    128
#define NT    512
#define NCTA  ((EDGES + BE - 1) / BE)   // 4883

// ---------------- smem layout (bytes) ----------------
// A chunk (k64, fp16 natural+swizzle): 128 rows x 128B = 16384 ; x2
// H (fp16 natural+swizzle): 128 rows x 256B = 32768
#define SM_A0   0
#define SM_A1   16384
#define SM_H    32768
#define SM_PART 65536          // 128 rows x 4 x float2 = 4096
#define SM_P    69632
#define P_B1    (SM_P + 0)
#define P_B2    (SM_P + 512)
#define P_G     (SM_P + 1024)
#define P_BT    (SM_P + 1536)
#define P_SEND  (SM_P + 2048)
#define P_RECV  (SM_P + 2560)
#define SMEM_ALLOC 73728

// weights in fp16 m16n8k16 B-fragment layout (verified R6/R7):
// block(kstep16, ntile8) = 256B: uint32 slot = lane*2 + r ; lane=(g<<2)|t
//   slot lo/hi = W[k][n], W[k+1][n]  with k = ks*16 + r*8 + t*2 , n = nt*8 + g
// slice (kstep16) stride = 16 blocks * 64 uint32 = 1024 uint32
__device__ __align__(16) uint32_t g_W1F[24 * 16 * 64];
__device__ __align__(16) uint32_t g_W2F[8 * 16 * 64];

__device__ __forceinline__ uint32_t packf16(float lo, float hi) {
    uint32_t u;
    asm("cvt.rn.f16x2.f32 %0, %1, %2;" : "=r"(u) : "f"(hi), "f"(lo));
    return u;
}

__global__ void prep_w_kernel(const float* __restrict__ W1,
                              const float* __restrict__ W2) {
    int i = blockIdx.x * 256 + threadIdx.x;
    if (i < 24 * 16 * 64) {
        int blk = i >> 6, w = i & 63;
        int lane = w >> 1, r = w & 1;
        int g = lane >> 2, t = lane & 3;
        int ks = blk >> 4, nt = blk & 15;
        int k = ks * 16 + r * 8 + t * 2;
        int n = nt * 8 + g;
        g_W1F[i] = packf16(W1[k * 128 + n], W1[(k + 1) * 128 + n]);
    }
    if (i < 8 * 16 * 64) {
        int blk = i >> 6, w = i & 63;
        int lane = w >> 1, r = w & 1;
        int g = lane >> 2, t = lane & 3;
        int ks = blk >> 4, nt = blk & 15;
        int k = ks * 16 + r * 8 + t * 2;
        int n = nt * 8 + g;
        g_W2F[i] = packf16(W2[k * 128 + n], W2[(k + 1) * 128 + n]);
    }
}

__device__ __forceinline__ void mma_fp16(float& c0, float& c1, float& c2, float& c3,
                                         uint32_t a0, uint32_t a1, uint32_t a2, uint32_t a3,
                                         uint32_t b0, uint32_t b1) {
    asm volatile("mma.sync.aligned.m16n8k16.row.col.f32.f16.f16.f32 "
                 "{%0,%1,%2,%3}, {%4,%5,%6,%7}, {%8,%9}, {%0,%1,%2,%3};"
                 : "+f"(c0), "+f"(c1), "+f"(c2), "+f"(c3)
                 : "r"(a0), "r"(a1), "r"(a2), "r"(a3), "r"(b0), "r"(b1));
}

__device__ __forceinline__ void ldsm4(uint32_t& r0, uint32_t& r1, uint32_t& r2, uint32_t& r3,
                                      uint32_t addr) {
    asm volatile("ldmatrix.sync.aligned.m8n8.x4.shared.b16 {%0,%1,%2,%3}, [%4];"
                 : "=r"(r0), "=r"(r1), "=r"(r2), "=r"(r3) : "r"(addr));
}

// per-half named barrier: id 1+h, 256 threads
#define HBAR(h) asm volatile("bar.sync %0, 256;" :: "r"(1 + (h)) : "memory")

__global__ __launch_bounds__(NT, 1) void edge_mlp_mma(
    const float* __restrict__ node_attr,
    const void*  __restrict__ eidx_raw,
    const float* __restrict__ edge_attr,
    const float* __restrict__ b1g,
    const float* __restrict__ b2g,
    const float* __restrict__ gg,
    const float* __restrict__ btg,
    float* __restrict__ out)
{
    extern __shared__ char smem[];
    uint32_t smb;
    asm("{ .reg .u64 t; cvta.to.shared.u64 t, %1; cvt.u32.u64 %0, t; }"
        : "=r"(smb) : "l"(smem));

    const int tid   = threadIdx.x;
    const int wid   = tid >> 5;
    const int lane  = tid & 31;
    const int g     = lane >> 2;
    const int t     = lane & 3;
    const int wm    = wid >> 2;    // 0..3 (M quarter); halves: wm{0,1} | wm{2,3}
    const int wn    = wid & 3;     // 0..3 (N quarter, 32 cols)
    const int h     = tid >> 8;    // half id
    const int ht    = tid & 255;   // thread-in-half
    const int e0    = blockIdx.x * BE;
    const int lrow7 = lane & 7;
    const int rowb  = wm * 32 + lrow7 + 8 * ((lane >> 3) & 1);
    const int grx   = (lane >> 4) & 1;

    // this warp's B-fragment lane slot within a slice
    const int wslot = (wn * 4) * 64 + lane * 2;
    const uint32_t* wp = g_W1F + wslot;          // points at slice to prefetch next

    // prefetch slice 0 into bn; wp -> slice 1
    uint2 bn[4];
    #pragma unroll
    for (int j = 0; j < 4; j++) bn[j] = *(const uint2*)(wp + j * 64);
    wp += 1024;

    if (tid < 128) {
        ((float*)(smem + P_B1))[tid] = b1g[tid];
        ((float*)(smem + P_B2))[tid] = b2g[tid];
        ((float*)(smem + P_G ))[tid] = gg[tid];
        ((float*)(smem + P_BT))[tid] = btg[tid];
    }
    const int* raw32 = (const int*)eidx_raw;
    bool is64 = true;
    #pragma unroll
    for (int i = 0; i < 16; i++) is64 &= (raw32[2 * i + 1] == 0);
    if (tid < BE) {
        int eg = e0 + tid; if (eg >= EDGES) eg = EDGES - 1;
        int s, r;
        if (is64) { const long long* p = (const long long*)eidx_raw;
                    s = (int)p[eg]; r = (int)p[EDGES + eg]; }
        else      { s = raw32[eg]; r = raw32[EDGES + eg]; }
        ((int*)(smem + P_SEND))[tid] = s;
        ((int*)(smem + P_RECV))[tid] = r;
    }
    __syncthreads();   // send/recv + params visible (only full barrier)

    const int* sSend = (const int*)(smem + P_SEND);
    const int* sRecv = (const int*)(smem + P_RECV);

    // prefetch A chunk 0 (sender, k 0..63): half-local 1024 float4 slots
    float4 prA[4];
    #pragma unroll
    for (int it = 0; it < 4; it++) {
        int idx = ht + it * 256;
        int row = h * 64 + (idx >> 4), jc = idx & 15;
        prA[it] = *(const float4*)(node_attr + (size_t)sSend[row] * DD + jc * 4);
    }

    float acc[2][4][4];
    #pragma unroll
    for (int i = 0; i < 2; i++)
        #pragma unroll
        for (int j = 0; j < 4; j++)
            #pragma unroll
            for (int r = 0; r < 4; r++) acc[i][j][r] = 0.0f;

    // =================== GEMM1: 6 chunks of k=64 ===================
    #pragma unroll 1
    for (int c = 0; c < 6; c++) {
        const uint32_t aoff = (c & 1) ? SM_A1 : SM_A0;
        char* abuf = smem + aoff;
        // scatter A(c): own half's rows, natural fp16 + XOR swizzle
        #pragma unroll
        for (int it = 0; it < 4; it++) {
            int idx = ht + it * 256;
            int row = h * 64 + (idx >> 4), jc = idx & 15;
            int sw = (jc >> 1) ^ (row & 7);
            uint2 v;
            v.x = packf16(prA[it].x, prA[it].y);
            v.y = packf16(prA[it].z, prA[it].w);
            *(uint2*)(abuf + row * 128 + sw * 16 + (jc & 1) * 8) = v;
        }
        HBAR(h);         // half's A(c) visible; half's MMA(c-1) done

        if (c < 5) {     // prefetch A(c+1)
            int cn = c + 1;
            #pragma unroll
            for (int it = 0; it < 4; it++) {
                int idx = ht + it * 256;
                int row = h * 64 + (idx >> 4), jc = idx & 15;
                const float* src;
                if (cn < 2)      src = node_attr + (size_t)sSend[row] * DD + cn * 64;
                else if (cn < 4) src = node_attr + (size_t)sRecv[row] * DD + (cn - 2) * 64;
                else { int eg = e0 + row; if (eg >= EDGES) eg = EDGES - 1;
                       src = edge_attr + (size_t)eg * DD + (cn - 4) * 64; }
                prA[it] = *(const float4*)(src + jc * 4);
            }
        }

        const uint32_t abase = smb + aoff;
        #pragma unroll
        for (int s = 0; s < 4; s++) {
            uint2 b[4];
            #pragma unroll
            for (int j = 0; j < 4; j++) b[j] = bn[j];
            // prefetch next slice; at (c=5,s=3) the next slice is W2F slice 0
            if (s == 3 && c == 5) wp = g_W2F + wslot;
            #pragma unroll
            for (int j = 0; j < 4; j++) bn[j] = *(const uint2*)(wp + j * 64);
            wp += 1024;
            #pragma unroll
            for (int i = 0; i < 2; i++) {
                uint32_t a0, a1, a2, a3;
                uint32_t ad = abase + (rowb + i * 16) * 128 +
                              (((s * 2 + grx) ^ lrow7) << 4);
                ldsm4(a0, a1, a2, a3, ad);
                #pragma unroll
                for (int j = 0; j < 4; j++)
                    mma_fp16(acc[i][j][0], acc[i][j][1], acc[i][j][2], acc[i][j][3],
                             a0, a1, a2, a3, b[j].x, b[j].y);
            }
        }
    }

    // ========== epilogue1: bias + ReLU -> H (own half rows) ==========
    {
        const float* B1 = (const float*)(smem + P_B1);
        #pragma unroll
        for (int i = 0; i < 2; i++) {
            int row_lo = wm * 32 + i * 16 + g;
            #pragma unroll
            for (int j = 0; j < 4; j++) {
                int col = wn * 32 + j * 8 + 2 * t;
                float x0 = fmaxf(acc[i][j][0] + B1[col],     0.0f);
                float x1 = fmaxf(acc[i][j][1] + B1[col + 1], 0.0f);
                float x2 = fmaxf(acc[i][j][2] + B1[col],     0.0f);
                float x3 = fmaxf(acc[i][j][3] + B1[col + 1], 0.0f);
                int swg = ((wn * 4 + j) ^ g) * 16 + 4 * t;
                *(uint32_t*)(smem + SM_H + row_lo * 256 + swg)       = packf16(x0, x1);
                *(uint32_t*)(smem + SM_H + (row_lo + 8) * 256 + swg) = packf16(x2, x3);
                acc[i][j][0] = 0.0f; acc[i][j][1] = 0.0f;
                acc[i][j][2] = 0.0f; acc[i][j][3] = 0.0f;
            }
        }
    }
    HBAR(h);           // half's H rows visible

    // ====== GEMM2: 2 chunks of k=64, A via LDSM from H, B in registers ======
    #pragma unroll
    for (int c2 = 0; c2 < 2; c2++) {
        #pragma unroll
        for (int s = 0; s < 4; s++) {
            uint2 b[4];
            #pragma unroll
            for (int j = 0; j < 4; j++) b[j] = bn[j];
            if (!(c2 == 1 && s == 3)) {     // last slice has nothing to prefetch
                #pragma unroll
                for (int j = 0; j < 4; j++) bn[j] = *(const uint2*)(wp + j * 64);
                wp += 1024;
            }
            #pragma unroll
            for (int i = 0; i < 2; i++) {
                uint32_t a0, a1, a2, a3;
                uint32_t ad = smb + SM_H + (rowb + i * 16) * 256 +
                              (((c2 * 8 + s * 2 + grx) ^ lrow7) << 4);
                ldsm4(a0, a1, a2, a3, ad);
                #pragma unroll
                for (int j = 0; j < 4; j++)
                    mma_fp16(acc[i][j][0], acc[i][j][1], acc[i][j][2], acc[i][j][3],
                             a0, a1, a2, a3, b[j].x, b[j].y);
            }
        }
    }

    // ========== bias2 + LayerNorm from registers (own half rows) ==========
    {
        const float* B2 = (const float*)(smem + P_B2);
        #pragma unroll
        for (int i = 0; i < 2; i++)
            #pragma unroll
            for (int j = 0; j < 4; j++) {
                int col = wn * 32 + j * 8 + 2 * t;
                acc[i][j][0] += B2[col];     acc[i][j][1] += B2[col + 1];
                acc[i][j][2] += B2[col];     acc[i][j][3] += B2[col + 1];
            }
        float2* part = (float2*)(smem + SM_PART);   // [row][wn]
        #pragma unroll
        for (int i = 0; i < 2; i++)
            #pragma unroll
            for (int hi = 0; hi < 2; hi++) {
                float s = 0.0f, q = 0.0f;
                #pragma unroll
                for (int j = 0; j < 4; j++) {
                    float v0 = acc[i][j][hi * 2], v1 = acc[i][j][hi * 2 + 1];
                    s += v0 + v1; q += v0 * v0 + v1 * v1;
                }
                s += __shfl_xor_sync(0xffffffffu, s, 1);
                q += __shfl_xor_sync(0xffffffffu, q, 1);
                s += __shfl_xor_sync(0xffffffffu, s, 2);
                q += __shfl_xor_sync(0xffffffffu, q, 2);
                if (t == 0) {
                    int row = wm * 32 + i * 16 + g + 8 * hi;
                    part[row * 4 + wn] = make_float2(s, q);
                }
            }
    }
    HBAR(h);           // half's partials visible

    {
        const float* G  = (const float*)(smem + P_G);
        const float* Bt = (const float*)(smem + P_BT);
        const float2* part = (const float2*)(smem + SM_PART);
        #pragma unroll
        for (int i = 0; i < 2; i++)
            #pragma unroll
            for (int hi = 0; hi < 2; hi++) {
                int row = wm * 32 + i * 16 + g + 8 * hi;
                float2 p0 = part[row * 4 + 0], p1 = part[row * 4 + 1];
                float2 p2 = part[row * 4 + 2], p3 = part[row * 4 + 3];
                float sum = p0.x + p1.x + p2.x + p3.x;
                float sq  = p0.y + p1.y + p2.y + p3.y;
                float mu  = sum * (1.0f / 128.0f);
                float var = sq * (1.0f / 128.0f) - mu * mu;
                float rs  = rsqrtf(var + 1e-5f);
                int eg = e0 + row;
                if (eg < EDGES) {
                    float* o = out + (size_t)eg * DD;
                    #pragma unroll
                    for (int j = 0; j < 4; j++) {
                        int col = wn * 32 + j * 8 + 2 * t;
                        float2 v;
                        v.x = (acc[i][j][hi * 2]     - mu) * rs * G[col]     + Bt[col];
                        v.y = (acc[i][j][hi * 2 + 1] - mu) * rs * G[col + 1] + Bt[col + 1];
                        *(float2*)(o + col) = v;
                    }
                }
            }
    }
}

extern "C" void kernel_launch(void* const* d_in, const int* in_sizes, int n_in,
                              void* d_out, int out_size) {
    const float* node_attr = (const float*)d_in[0];
    const void*  eidx      = d_in[1];
    const float* edge_attr = (const float*)d_in[2];
    const float* W1        = (const float*)d_in[3];
    const float* b1        = (const float*)d_in[4];
    const float* W2        = (const float*)d_in[5];
    const float* b2        = (const float*)d_in[6];
    const float* gamma_    = (const float*)d_in[7];
    const float* beta_     = (const float*)d_in[8];

    cudaFuncSetAttribute(edge_mlp_mma, cudaFuncAttributeMaxDynamicSharedMemorySize, SMEM_ALLOC);

    prep_w_kernel<<<96, 256>>>(W1, W2);
    edge_mlp_mma<<<NCTA, NT, SMEM_ALLOC>>>(node_attr, eidx, edge_attr,
                                           b1, b2, gamma_, beta_, (float*)d_out);
}

// round 15
// speedup vs baseline: 1.2655x; 1.2292x over previous
#include <cuda_runtime.h>
#include <cstdint>

#define EDGES 625000
#define DD    128
#define BE    128
#define NT    512
#define NCTA  ((EDGES + BE - 1) / BE)   // 4883
#define GRID  152                        // persistent: 1 CTA per SM (GB300 = 152 SMs)

// ---------------- smem layout (bytes) ----------------
#define SM_A0   0
#define SM_A1   16384
#define SM_B    32768          // resident B: 32 slices x 16 nt x 256B = 131072
#define SM_H    163840         // 128 rows x 256B = 32768
#define SM_PART 196608         // 128 rows x 4 x float2 = 4096
#define SM_P    200704
#define P_B1    (SM_P + 0)
#define P_B2    (SM_P + 512)
#define P_G     (SM_P + 1024)
#define P_BT    (SM_P + 1536)
#define P_SEND  (SM_P + 2048)
#define P_RECV  (SM_P + 2560)
#define SMEM_ALLOC 204800

// weights in fp16 m16n8k16 B-fragment layout (verified R6+):
// block(kstep16, ntile8) = 256B: uint32 slot = lane*2 + r ; lane=(g<<2)|t
//   slot lo/hi = W[k][n], W[k+1][n]  with k = ks*16 + r*8 + t*2 , n = nt*8 + g
__device__ __align__(16) uint32_t g_W1F[24 * 16 * 64];
__device__ __align__(16) uint32_t g_W2F[8 * 16 * 64];

__device__ __forceinline__ uint32_t packf16(float lo, float hi) {
    uint32_t u;
    asm("cvt.rn.f16x2.f32 %0, %1, %2;" : "=r"(u) : "f"(hi), "f"(lo));
    return u;
}

__global__ void prep_w_kernel(const float* __restrict__ W1,
                              const float* __restrict__ W2) {
    int i = blockIdx.x * 256 + threadIdx.x;
    if (i < 24 * 16 * 64) {
        int blk = i >> 6, w = i & 63;
        int lane = w >> 1, r = w & 1;
        int g = lane >> 2, t = lane & 3;
        int ks = blk >> 4, nt = blk & 15;
        int k = ks * 16 + r * 8 + t * 2;
        int n = nt * 8 + g;
        g_W1F[i] = packf16(W1[k * 128 + n], W1[(k + 1) * 128 + n]);
    }
    if (i < 8 * 16 * 64) {
        int blk = i >> 6, w = i & 63;
        int lane = w >> 1, r = w & 1;
        int g = lane >> 2, t = lane & 3;
        int ks = blk >> 4, nt = blk & 15;
        int k = ks * 16 + r * 8 + t * 2;
        int n = nt * 8 + g;
        g_W2F[i] = packf16(W2[k * 128 + n], W2[(k + 1) * 128 + n]);
    }
}

__device__ __forceinline__ void mma_fp16(float& c0, float& c1, float& c2, float& c3,
                                         uint32_t a0, uint32_t a1, uint32_t a2, uint32_t a3,
                                         uint32_t b0, uint32_t b1) {
    asm volatile("mma.sync.aligned.m16n8k16.row.col.f32.f16.f16.f32 "
                 "{%0,%1,%2,%3}, {%4,%5,%6,%7}, {%8,%9}, {%0,%1,%2,%3};"
                 : "+f"(c0), "+f"(c1), "+f"(c2), "+f"(c3)
                 : "r"(a0), "r"(a1), "r"(a2), "r"(a3), "r"(b0), "r"(b1));
}

__device__ __forceinline__ void ldsm4(uint32_t& r0, uint32_t& r1, uint32_t& r2, uint32_t& r3,
                                      uint32_t addr) {
    asm volatile("ldmatrix.sync.aligned.m8n8.x4.shared.b16 {%0,%1,%2,%3}, [%4];"
                 : "=r"(r0), "=r"(r1), "=r"(r2), "=r"(r3) : "r"(addr));
}

__device__ __forceinline__ void cp16(uint32_t saddr, const void* gptr) {
    asm volatile("cp.async.cg.shared.global [%0], [%1], 16;"
                 :: "r"(saddr), "l"(gptr));
}
#define CP_COMMIT() asm volatile("cp.async.commit_group;" ::: "memory")
#define CP_WAIT(n)  asm volatile("cp.async.wait_group %0;" :: "n"(n) : "memory")
// per-half named barrier: id 1+h, 256 threads
#define HBAR(h) asm volatile("bar.sync %0, 256;" :: "r"(1 + (h)) : "memory")

__global__ __launch_bounds__(NT, 1) void edge_mlp_mma(
    const float* __restrict__ node_attr,
    const void*  __restrict__ eidx_raw,
    const float* __restrict__ edge_attr,
    const float* __restrict__ b1g,
    const float* __restrict__ b2g,
    const float* __restrict__ gg,
    const float* __restrict__ btg,
    float* __restrict__ out)
{
    extern __shared__ char smem[];
    uint32_t smb;
    asm("{ .reg .u64 t; cvta.to.shared.u64 t, %1; cvt.u32.u64 %0, t; }"
        : "=r"(smb) : "l"(smem));

    const int tid   = threadIdx.x;
    const int wid   = tid >> 5;
    const int lane  = tid & 31;
    const int g     = lane >> 2;
    const int t     = lane & 3;
    const int wm    = wid >> 2;    // 0..3 (M quarter); halves: wm{0,1} | wm{2,3}
    const int wn    = wid & 3;     // 0..3 (N quarter, 32 cols)
    const int h     = tid >> 8;    // half id
    const int ht    = tid & 255;   // thread-in-half
    const int lrow7 = lane & 7;
    const int rowb  = wm * 32 + lrow7 + 8 * ((lane >> 3) & 1);
    const int grx   = (lane >> 4) & 1;

    // ---- one-time: fill resident B (128KB = 8192 x 16B slots, 16/thread) ----
    #pragma unroll
    for (int it = 0; it < 16; it++) {
        int idx = tid + it * NT;
        const uint32_t* src = (idx < 6144) ? (g_W1F + idx * 4)
                                           : (g_W2F + (idx - 6144) * 4);
        cp16(smb + SM_B + idx * 16, src);
    }
    CP_COMMIT();

    if (tid < 128) {
        ((float*)(smem + P_B1))[tid] = b1g[tid];
        ((float*)(smem + P_B2))[tid] = b2g[tid];
        ((float*)(smem + P_G ))[tid] = gg[tid];
        ((float*)(smem + P_BT))[tid] = btg[tid];
    }
    const int* raw32 = (const int*)eidx_raw;
    bool is64 = true;
    #pragma unroll
    for (int i = 0; i < 16; i++) is64 &= (raw32[2 * i + 1] == 0);
    CP_WAIT(0);
    __syncthreads();   // B + params resident (only full barrier)

    const int* sSend = (const int*)(smem + P_SEND);
    const int* sRecv = (const int*)(smem + P_RECV);
    const float* B1c = (const float*)(smem + P_B1);
    const float* B2c = (const float*)(smem + P_B2);
    const float* Gc  = (const float*)(smem + P_G);
    const float* Btc = (const float*)(smem + P_BT);

    // =========================== persistent tile loop ===========================
    #pragma unroll 1
    for (int tile = blockIdx.x; tile < NCTA; tile += GRID) {
        const int e0 = tile * BE;

        // half-local index load: half h writes rows h*64 .. h*64+63
        if (ht < 64) {
            int row = h * 64 + ht;
            int eg = e0 + row; if (eg >= EDGES) eg = EDGES - 1;
            int s, r;
            if (is64) { const long long* p = (const long long*)eidx_raw;
                        s = (int)p[eg]; r = (int)p[EDGES + eg]; }
            else      { s = raw32[eg]; r = raw32[EDGES + eg]; }
            ((int*)(smem + P_SEND))[row] = s;
            ((int*)(smem + P_RECV))[row] = r;
        }
        HBAR(h);       // half's indices visible

        // prefetch A chunk 0 (sender, k 0..63): half-local 1024 float4 slots
        float4 prA[4];
        #pragma unroll
        for (int it = 0; it < 4; it++) {
            int idx = ht + it * 256;
            int row = h * 64 + (idx >> 4), jc = idx & 15;
            prA[it] = *(const float4*)(node_attr + (size_t)sSend[row] * DD + jc * 4);
        }

        float acc[2][4][4];
        #pragma unroll
        for (int i = 0; i < 2; i++)
            #pragma unroll
            for (int j = 0; j < 4; j++)
                #pragma unroll
                for (int r = 0; r < 4; r++) acc[i][j][r] = 0.0f;

        // ---------------- GEMM1: 6 chunks of k=64, B resident ----------------
        #pragma unroll 1
        for (int c = 0; c < 6; c++) {
            const uint32_t aoff = (c & 1) ? SM_A1 : SM_A0;
            char* abuf = smem + aoff;
            // scatter A(c): own half's rows, natural fp16 + XOR swizzle
            #pragma unroll
            for (int it = 0; it < 4; it++) {
                int idx = ht + it * 256;
                int row = h * 64 + (idx >> 4), jc = idx & 15;
                int sw = (jc >> 1) ^ (row & 7);
                uint2 v;
                v.x = packf16(prA[it].x, prA[it].y);
                v.y = packf16(prA[it].z, prA[it].w);
                *(uint2*)(abuf + row * 128 + sw * 16 + (jc & 1) * 8) = v;
            }
            HBAR(h);     // half's A(c) visible; half's MMA(c-1) done

            if (c < 5) { // prefetch A(c+1)
                int cn = c + 1;
                #pragma unroll
                for (int it = 0; it < 4; it++) {
                    int idx = ht + it * 256;
                    int row = h * 64 + (idx >> 4), jc = idx & 15;
                    const float* src;
                    if (cn < 2)      src = node_attr + (size_t)sSend[row] * DD + cn * 64;
                    else if (cn < 4) src = node_attr + (size_t)sRecv[row] * DD + (cn - 2) * 64;
                    else { int eg = e0 + row; if (eg >= EDGES) eg = EDGES - 1;
                           src = edge_attr + (size_t)eg * DD + (cn - 4) * 64; }
                    prA[it] = *(const float4*)(src + jc * 4);
                }
            }

            const char* bb = smem + SM_B;
            const uint32_t abase = smb + aoff;
            #pragma unroll
            for (int s = 0; s < 4; s++) {
                uint2 b[4];
                #pragma unroll
                for (int j = 0; j < 4; j++)
                    b[j] = *(const uint2*)(bb + (((c * 4 + s) * 16) + wn * 4 + j) * 256 + lane * 8);
                #pragma unroll
                for (int i = 0; i < 2; i++) {
                    uint32_t a0, a1, a2, a3;
                    uint32_t ad = abase + (rowb + i * 16) * 128 +
                                  (((s * 2 + grx) ^ lrow7) << 4);
                    ldsm4(a0, a1, a2, a3, ad);
                    #pragma unroll
                    for (int j = 0; j < 4; j++)
                        mma_fp16(acc[i][j][0], acc[i][j][1], acc[i][j][2], acc[i][j][3],
                                 a0, a1, a2, a3, b[j].x, b[j].y);
                }
            }
        }

        // ---------- epilogue1: bias + ReLU -> H (own half rows) ----------
        #pragma unroll
        for (int i = 0; i < 2; i++) {
            int row_lo = wm * 32 + i * 16 + g;
            #pragma unroll
            for (int j = 0; j < 4; j++) {
                int col = wn * 32 + j * 8 + 2 * t;
                float x0 = fmaxf(acc[i][j][0] + B1c[col],     0.0f);
                float x1 = fmaxf(acc[i][j][1] + B1c[col + 1], 0.0f);
                float x2 = fmaxf(acc[i][j][2] + B1c[col],     0.0f);
                float x3 = fmaxf(acc[i][j][3] + B1c[col + 1], 0.0f);
                int swg = ((wn * 4 + j) ^ g) * 16 + 4 * t;
                *(uint32_t*)(smem + SM_H + row_lo * 256 + swg)       = packf16(x0, x1);
                *(uint32_t*)(smem + SM_H + (row_lo + 8) * 256 + swg) = packf16(x2, x3);
                acc[i][j][0] = 0.0f; acc[i][j][1] = 0.0f;
                acc[i][j][2] = 0.0f; acc[i][j][3] = 0.0f;
            }
        }
        HBAR(h);       // half's H rows visible

        // ---- GEMM2: 2 chunks of k=64, A via LDSM from H, B resident (ks 24..31) ----
        #pragma unroll
        for (int c2 = 0; c2 < 2; c2++) {
            const char* bb = smem + SM_B;
            #pragma unroll
            for (int s = 0; s < 4; s++) {
                uint2 b[4];
                #pragma unroll
                for (int j = 0; j < 4; j++)
                    b[j] = *(const uint2*)(bb + (((24 + c2 * 4 + s) * 16) + wn * 4 + j) * 256 + lane * 8);
                #pragma unroll
                for (int i = 0; i < 2; i++) {
                    uint32_t a0, a1, a2, a3;
                    uint32_t ad = smb + SM_H + (rowb + i * 16) * 256 +
                                  (((c2 * 8 + s * 2 + grx) ^ lrow7) << 4);
                    ldsm4(a0, a1, a2, a3, ad);
                    #pragma unroll
                    for (int j = 0; j < 4; j++)
                        mma_fp16(acc[i][j][0], acc[i][j][1], acc[i][j][2], acc[i][j][3],
                                 a0, a1, a2, a3, b[j].x, b[j].y);
                }
            }
        }

        // ---------- bias2 + LayerNorm from registers (own half rows) ----------
        {
            #pragma unroll
            for (int i = 0; i < 2; i++)
                #pragma unroll
                for (int j = 0; j < 4; j++) {
                    int col = wn * 32 + j * 8 + 2 * t;
                    acc[i][j][0] += B2c[col];     acc[i][j][1] += B2c[col + 1];
                    acc[i][j][2] += B2c[col];     acc[i][j][3] += B2c[col + 1];
                }
            float2* part = (float2*)(smem + SM_PART);   // [row][wn]
            #pragma unroll
            for (int i = 0; i < 2; i++)
                #pragma unroll
                for (int hi = 0; hi < 2; hi++) {
                    float s = 0.0f, q = 0.0f;
                    #pragma unroll
                    for (int j = 0; j < 4; j++) {
                        float v0 = acc[i][j][hi * 2], v1 = acc[i][j][hi * 2 + 1];
                        s += v0 + v1; q += v0 * v0 + v1 * v1;
                    }
                    s += __shfl_xor_sync(0xffffffffu, s, 1);
                    q += __shfl_xor_sync(0xffffffffu, q, 1);
                    s += __shfl_xor_sync(0xffffffffu, s, 2);
                    q += __shfl_xor_sync(0xffffffffu, q, 2);
                    if (t == 0) {
                        int row = wm * 32 + i * 16 + g + 8 * hi;
                        part[row * 4 + wn] = make_float2(s, q);
                    }
                }
        }
        HBAR(h);       // half's partials visible

        {
            const float2* part = (const float2*)(smem + SM_PART);
            #pragma unroll
            for (int i = 0; i < 2; i++)
                #pragma unroll
                for (int hi = 0; hi < 2; hi++) {
                    int row = wm * 32 + i * 16 + g + 8 * hi;
                    float2 p0 = part[row * 4 + 0], p1 = part[row * 4 + 1];
                    float2 p2 = part[row * 4 + 2], p3 = part[row * 4 + 3];
                    float sum = p0.x + p1.x + p2.x + p3.x;
                    float sq  = p0.y + p1.y + p2.y + p3.y;
                    float mu  = sum * (1.0f / 128.0f);
                    float var = sq * (1.0f / 128.0f) - mu * mu;
                    float rs  = rsqrtf(var + 1e-5f);
                    int eg = e0 + row;
                    if (eg < EDGES) {
                        float* o = out + (size_t)eg * DD;
                        #pragma unroll
                        for (int j = 0; j < 4; j++) {
                            int col = wn * 32 + j * 8 + 2 * t;
                            float2 v;
                            v.x = (acc[i][j][hi * 2]     - mu) * rs * Gc[col]     + Btc[col];
                            v.y = (acc[i][j][hi * 2 + 1] - mu) * rs * Gc[col + 1] + Btc[col + 1];
                            *(float2*)(o + col) = v;
                        }
                    }
                }
        }
        HBAR(h);       // part reads done before next tile overwrites; sSend rewrite safe
    }
}

extern "C" void kernel_launch(void* const* d_in, const int* in_sizes, int n_in,
                              void* d_out, int out_size) {
    const float* node_attr = (const float*)d_in[0];
    const void*  eidx      = d_in[1];
    const float* edge_attr = (const float*)d_in[2];
    const float* W1        = (const float*)d_in[3];
    const float* b1        = (const float*)d_in[4];
    const float* W2        = (const float*)d_in[5];
    const float* b2        = (const float*)d_in[6];
    const float* gamma_    = (const float*)d_in[7];
    const float* beta_     = (const float*)d_in[8];

    cudaFuncSetAttribute(edge_mlp_mma, cudaFuncAttributeMaxDynamicSharedMemorySize, SMEM_ALLOC);

    prep_w_kernel<<<96, 256>>>(W1, W2);
    edge_mlp_mma<<<GRID, NT, SMEM_ALLOC>>>(node_attr, eidx, edge_attr,
                                           b1, b2, gamma_, beta_, (float*)d_out);
}

// round 16
// speedup vs baseline: 1.2855x; 1.0158x over previous
#include <cuda_runtime.h>
#include <cstdint>

#define EDGES  625000
#define NODES  50000
#define DD     128
#define BE     128
#define NT     512
#define NCTA   ((EDGES + BE - 1) / BE)   // 4883
#define GRID   152                       // persistent: 1 CTA per SM

// ---------------- smem layout (bytes) ----------------
#define SM_A0   0
#define SM_A1   16384
#define SM_B    32768          // resident B: 32 slices x 16 nt x 256B = 131072
#define SM_H    163840         // 128 rows x 256B = 32768
#define SM_PART 196608         // 128 rows x 4 x float2 = 4096
#define SM_P    200704
#define P_B1    (SM_P + 0)
#define P_B2    (SM_P + 512)
#define P_G     (SM_P + 1024)
#define P_BT    (SM_P + 1536)
#define P_SEND  (SM_P + 2048)
#define P_RECV  (SM_P + 2560)
#define SMEM_ALLOC 204800

// weights in fp16 m16n8k16 B-fragment layout (verified R6+)
__device__ __align__(16) uint32_t g_W1F[24 * 16 * 64];
__device__ __align__(16) uint32_t g_W2F[8 * 16 * 64];
// node_attr pre-converted to fp16 (uint32 = fp16x2), natural row-major
__device__ __align__(16) uint32_t g_node16[NODES * 64];   // 12.8MB

__device__ __forceinline__ uint32_t packf16(float lo, float hi) {
    uint32_t u;
    asm("cvt.rn.f16x2.f32 %0, %1, %2;" : "=r"(u) : "f"(hi), "f"(lo));
    return u;
}

__global__ void prep_w_kernel(const float* __restrict__ W1,
                              const float* __restrict__ W2) {
    int i = blockIdx.x * 256 + threadIdx.x;
    if (i < 24 * 16 * 64) {
        int blk = i >> 6, w = i & 63;
        int lane = w >> 1, r = w & 1;
        int g = lane >> 2, t = lane & 3;
        int ks = blk >> 4, nt = blk & 15;
        int k = ks * 16 + r * 8 + t * 2;
        int n = nt * 8 + g;
        g_W1F[i] = packf16(W1[k * 128 + n], W1[(k + 1) * 128 + n]);
    }
    if (i < 8 * 16 * 64) {
        int blk = i >> 6, w = i & 63;
        int lane = w >> 1, r = w & 1;
        int g = lane >> 2, t = lane & 3;
        int ks = blk >> 4, nt = blk & 15;
        int k = ks * 16 + r * 8 + t * 2;
        int n = nt * 8 + g;
        g_W2F[i] = packf16(W2[k * 128 + n], W2[(k + 1) * 128 + n]);
    }
}

__global__ void prep_node_kernel(const float* __restrict__ node_attr) {
    int i = blockIdx.x * 256 + threadIdx.x;          // over 3.2M fp16x2 slots
    if (i < NODES * 64) {
        float2 v = *(const float2*)(node_attr + i * 2);
        g_node16[i] = packf16(v.x, v.y);
    }
}

__device__ __forceinline__ void mma_fp16(float& c0, float& c1, float& c2, float& c3,
                                         uint32_t a0, uint32_t a1, uint32_t a2, uint32_t a3,
                                         uint32_t b0, uint32_t b1) {
    asm volatile("mma.sync.aligned.m16n8k16.row.col.f32.f16.f16.f32 "
                 "{%0,%1,%2,%3}, {%4,%5,%6,%7}, {%8,%9}, {%0,%1,%2,%3};"
                 : "+f"(c0), "+f"(c1), "+f"(c2), "+f"(c3)
                 : "r"(a0), "r"(a1), "r"(a2), "r"(a3), "r"(b0), "r"(b1));
}

__device__ __forceinline__ void ldsm4(uint32_t& r0, uint32_t& r1, uint32_t& r2, uint32_t& r3,
                                      uint32_t addr) {
    asm volatile("ldmatrix.sync.aligned.m8n8.x4.shared.b16 {%0,%1,%2,%3}, [%4];"
                 : "=r"(r0), "=r"(r1), "=r"(r2), "=r"(r3) : "r"(addr));
}

__device__ __forceinline__ void cp16(uint32_t saddr, const void* gptr) {
    asm volatile("cp.async.cg.shared.global [%0], [%1], 16;"
                 :: "r"(saddr), "l"(gptr));
}
#define CP_COMMIT() asm volatile("cp.async.commit_group;" ::: "memory")
#define CP_WAIT(n)  asm volatile("cp.async.wait_group %0;" :: "n"(n) : "memory")
#define HBAR(h) asm volatile("bar.sync %0, 256;" :: "r"(1 + (h)) : "memory")

__global__ __launch_bounds__(NT, 1) void edge_mlp_mma(
    const float* __restrict__ node_attr,
    const void*  __restrict__ eidx_raw,
    const float* __restrict__ edge_attr,
    const float* __restrict__ b1g,
    const float* __restrict__ b2g,
    const float* __restrict__ gg,
    const float* __restrict__ btg,
    float* __restrict__ out)
{
    extern __shared__ char smem[];
    uint32_t smb;
    asm("{ .reg .u64 t; cvta.to.shared.u64 t, %1; cvt.u32.u64 %0, t; }"
        : "=r"(smb) : "l"(smem));

    const int tid   = threadIdx.x;
    const int wid   = tid >> 5;
    const int lane  = tid & 31;
    const int g     = lane >> 2;
    const int t     = lane & 3;
    const int wm    = wid >> 2;    // 0..3 (M quarter); halves: wm{0,1} | wm{2,3}
    const int wn    = wid & 3;     // 0..3 (N quarter, 32 cols)
    const int h     = tid >> 8;
    const int ht    = tid & 255;
    const int lrow7 = lane & 7;
    const int rowb  = wm * 32 + lrow7 + 8 * ((lane >> 3) & 1);
    const int grx   = (lane >> 4) & 1;

    // ---- one-time: fill resident B (128KB) ----
    #pragma unroll
    for (int it = 0; it < 16; it++) {
        int idx = tid + it * NT;
        const uint32_t* src = (idx < 6144) ? (g_W1F + idx * 4)
                                           : (g_W2F + (idx - 6144) * 4);
        cp16(smb + SM_B + idx * 16, src);
    }
    CP_COMMIT();

    if (tid < 128) {
        ((float*)(smem + P_B1))[tid] = b1g[tid];
        ((float*)(smem + P_B2))[tid] = b2g[tid];
        ((float*)(smem + P_G ))[tid] = gg[tid];
        ((float*)(smem + P_BT))[tid] = btg[tid];
    }
    const int* raw32 = (const int*)eidx_raw;
    bool is64 = true;
    #pragma unroll
    for (int i = 0; i < 16; i++) is64 &= (raw32[2 * i + 1] == 0);
    CP_WAIT(0);
    __syncthreads();   // B + params resident (only full barrier)

    const int* sSend = (const int*)(smem + P_SEND);
    const int* sRecv = (const int*)(smem + P_RECV);
    const float* B1c = (const float*)(smem + P_B1);
    const float* B2c = (const float*)(smem + P_B2);
    const float* Gc  = (const float*)(smem + P_G);
    const float* Btc = (const float*)(smem + P_BT);
    const char*  nbase = (const char*)g_node16;

    // =========================== persistent tile loop ===========================
    #pragma unroll 1
    for (int tile = blockIdx.x; tile < NCTA; tile += GRID) {
        const int e0 = tile * BE;

        // half-local index load
        if (ht < 64) {
            int row = h * 64 + ht;
            int eg = e0 + row; if (eg >= EDGES) eg = EDGES - 1;
            int s, r;
            if (is64) { const long long* p = (const long long*)eidx_raw;
                        s = (int)p[eg]; r = (int)p[EDGES + eg]; }
            else      { s = raw32[eg]; r = raw32[EDGES + eg]; }
            ((int*)(smem + P_SEND))[row] = s;
            ((int*)(smem + P_RECV))[row] = r;
        }
        HBAR(h);       // half's indices visible; prev tile fully done

        // issue cp.async A(0): sender k0..63 -> A0 (half-local 512 slots, 2/thread)
        #pragma unroll
        for (int it = 0; it < 2; it++) {
            int idx = ht + it * 256;
            int row = h * 64 + (idx >> 3), jc2 = idx & 7;
            const char* src = nbase + (size_t)sSend[row] * 256 + jc2 * 16;
            cp16(smb + SM_A0 + row * 128 + ((jc2 ^ (row & 7)) << 4), src);
        }
        CP_COMMIT();

        float4 prA[4];
        float acc[2][4][4];
        #pragma unroll
        for (int i = 0; i < 2; i++)
            #pragma unroll
            for (int j = 0; j < 4; j++)
                #pragma unroll
                for (int r = 0; r < 4; r++) acc[i][j][r] = 0.0f;

        // ---------------- GEMM1: 6 chunks of k=64 ----------------
        #pragma unroll 1
        for (int c = 0; c < 6; c++) {
            const uint32_t aoff = (c & 1) ? SM_A1 : SM_A0;
            if (c < 4) {
                CP_WAIT(0);            // A(c) cp.async landed
            } else {
                // scatter edge chunk A(c) from prA (fp32 -> fp16, swizzled)
                char* abuf = smem + aoff;
                #pragma unroll
                for (int it = 0; it < 4; it++) {
                    int idx = ht + it * 256;
                    int row = h * 64 + (idx >> 4), jc = idx & 15;
                    int sw = (jc >> 1) ^ (row & 7);
                    uint2 v;
                    v.x = packf16(prA[it].x, prA[it].y);
                    v.y = packf16(prA[it].z, prA[it].w);
                    *(uint2*)(abuf + row * 128 + sw * 16 + (jc & 1) * 8) = v;
                }
            }
            HBAR(h);     // half's A(c) visible; half's MMA(c-1) done

            if (c < 3) {
                // issue cp.async A(c+1): node chunk
                int cn = c + 1;
                const int* nd = (cn < 2) ? sSend : sRecv;
                int koff = (cn & 1) * 128;     // byte offset within 256B row
                uint32_t dstb = smb + ((cn & 1) ? SM_A1 : SM_A0);
                #pragma unroll
                for (int it = 0; it < 2; it++) {
                    int idx = ht + it * 256;
                    int row = h * 64 + (idx >> 3), jc2 = idx & 7;
                    const char* src = nbase + (size_t)nd[row] * 256 + koff + jc2 * 16;
                    cp16(dstb + row * 128 + ((jc2 ^ (row & 7)) << 4), src);
                }
                CP_COMMIT();
            } else if (c < 5) {
                // LDG prefetch edge chunk A(c+1)
                int cn = c + 1;
                #pragma unroll
                for (int it = 0; it < 4; it++) {
                    int idx = ht + it * 256;
                    int row = h * 64 + (idx >> 4), jc = idx & 15;
                    int eg = e0 + row; if (eg >= EDGES) eg = EDGES - 1;
                    prA[it] = *(const float4*)(edge_attr + (size_t)eg * DD +
                                               (cn - 4) * 64 + jc * 4);
                }
            }

            const char* bb = smem + SM_B;
            const uint32_t abase = smb + aoff;
            #pragma unroll
            for (int s = 0; s < 4; s++) {
                uint2 b[4];
                #pragma unroll
                for (int j = 0; j < 4; j++)
                    b[j] = *(const uint2*)(bb + (((c * 4 + s) * 16) + wn * 4 + j) * 256 + lane * 8);
                #pragma unroll
                for (int i = 0; i < 2; i++) {
                    uint32_t a0, a1, a2, a3;
                    uint32_t ad = abase + (rowb + i * 16) * 128 +
                                  (((s * 2 + grx) ^ lrow7) << 4);
                    ldsm4(a0, a1, a2, a3, ad);
                    #pragma unroll
                    for (int j = 0; j < 4; j++)
                        mma_fp16(acc[i][j][0], acc[i][j][1], acc[i][j][2], acc[i][j][3],
                                 a0, a1, a2, a3, b[j].x, b[j].y);
                }
            }
        }

        // ---------- epilogue1: bias + ReLU -> H (own half rows) ----------
        #pragma unroll
        for (int i = 0; i < 2; i++) {
            int row_lo = wm * 32 + i * 16 + g;
            #pragma unroll
            for (int j = 0; j < 4; j++) {
                int col = wn * 32 + j * 8 + 2 * t;
                float x0 = fmaxf(acc[i][j][0] + B1c[col],     0.0f);
                float x1 = fmaxf(acc[i][j][1] + B1c[col + 1], 0.0f);
                float x2 = fmaxf(acc[i][j][2] + B1c[col],     0.0f);
                float x3 = fmaxf(acc[i][j][3] + B1c[col + 1], 0.0f);
                int swg = ((wn * 4 + j) ^ g) * 16 + 4 * t;
                *(uint32_t*)(smem + SM_H + row_lo * 256 + swg)       = packf16(x0, x1);
                *(uint32_t*)(smem + SM_H + (row_lo + 8) * 256 + swg) = packf16(x2, x3);
                acc[i][j][0] = 0.0f; acc[i][j][1] = 0.0f;
                acc[i][j][2] = 0.0f; acc[i][j][3] = 0.0f;
            }
        }
        HBAR(h);       // half's H rows visible

        // ---- GEMM2: 2 chunks, A via LDSM from H, B resident (ks 24..31) ----
        #pragma unroll
        for (int c2 = 0; c2 < 2; c2++) {
            const char* bb = smem + SM_B;
            #pragma unroll
            for (int s = 0; s < 4; s++) {
                uint2 b[4];
                #pragma unroll
                for (int j = 0; j < 4; j++)
                    b[j] = *(const uint2*)(bb + (((24 + c2 * 4 + s) * 16) + wn * 4 + j) * 256 + lane * 8);
                #pragma unroll
                for (int i = 0; i < 2; i++) {
                    uint32_t a0, a1, a2, a3;
                    uint32_t ad = smb + SM_H + (rowb + i * 16) * 256 +
                                  (((c2 * 8 + s * 2 + grx) ^ lrow7) << 4);
                    ldsm4(a0, a1, a2, a3, ad);
                    #pragma unroll
                    for (int j = 0; j < 4; j++)
                        mma_fp16(acc[i][j][0], acc[i][j][1], acc[i][j][2], acc[i][j][3],
                                 a0, a1, a2, a3, b[j].x, b[j].y);
                }
            }
        }

        // ---------- bias2 + LayerNorm from registers (own half rows) ----------
        {
            #pragma unroll
            for (int i = 0; i < 2; i++)
                #pragma unroll
                for (int j = 0; j < 4; j++) {
                    int col = wn * 32 + j * 8 + 2 * t;
                    acc[i][j][0] += B2c[col];     acc[i][j][1] += B2c[col + 1];
                    acc[i][j][2] += B2c[col];     acc[i][j][3] += B2c[col + 1];
                }
            float2* part = (float2*)(smem + SM_PART);   // [row][wn]
            #pragma unroll
            for (int i = 0; i < 2; i++)
                #pragma unroll
                for (int hi = 0; hi < 2; hi++) {
                    float s = 0.0f, q = 0.0f;
                    #pragma unroll
                    for (int j = 0; j < 4; j++) {
                        float v0 = acc[i][j][hi * 2], v1 = acc[i][j][hi * 2 + 1];
                        s += v0 + v1; q += v0 * v0 + v1 * v1;
                    }
                    s += __shfl_xor_sync(0xffffffffu, s, 1);
                    q += __shfl_xor_sync(0xffffffffu, q, 1);
                    s += __shfl_xor_sync(0xffffffffu, s, 2);
                    q += __shfl_xor_sync(0xffffffffu, q, 2);
                    if (t == 0) {
                        int row = wm * 32 + i * 16 + g + 8 * hi;
                        part[row * 4 + wn] = make_float2(s, q);
                    }
                }
        }
        HBAR(h);       // half's partials visible

        {
            const float2* part = (const float2*)(smem + SM_PART);
            #pragma unroll
            for (int i = 0; i < 2; i++)
                #pragma unroll
                for (int hi = 0; hi < 2; hi++) {
                    int row = wm * 32 + i * 16 + g + 8 * hi;
                    float2 p0 = part[row * 4 + 0], p1 = part[row * 4 + 1];
                    float2 p2 = part[row * 4 + 2], p3 = part[row * 4 + 3];
                    float sum = p0.x + p1.x + p2.x + p3.x;
                    float sq  = p0.y + p1.y + p2.y + p3.y;
                    float mu  = sum * (1.0f / 128.0f);
                    float var = sq * (1.0f / 128.0f) - mu * mu;
                    float rs  = rsqrtf(var + 1e-5f);
                    int eg = e0 + row;
                    if (eg < EDGES) {
                        float* o = out + (size_t)eg * DD;
                        #pragma unroll
                        for (int j = 0; j < 4; j++) {
                            int col = wn * 32 + j * 8 + 2 * t;
                            float2 v;
                            v.x = (acc[i][j][hi * 2]     - mu) * rs * Gc[col]     + Btc[col];
                            v.y = (acc[i][j][hi * 2 + 1] - mu) * rs * Gc[col + 1] + Btc[col + 1];
                            *(float2*)(o + col) = v;
                        }
                    }
                }
        }
        HBAR(h);       // tile fully done before next tile's index/A writes
    }
}

extern "C" void kernel_launch(void* const* d_in, const int* in_sizes, int n_in,
                              void* d_out, int out_size) {
    const float* node_attr = (const float*)d_in[0];
    const void*  eidx      = d_in[1];
    const float* edge_attr = (const float*)d_in[2];
    const float* W1        = (const float*)d_in[3];
    const float* b1        = (const float*)d_in[4];
    const float* W2        = (const float*)d_in[5];
    const float* b2        = (const float*)d_in[6];
    const float* gamma_    = (const float*)d_in[7];
    const float* beta_     = (const float*)d_in[8];

    cudaFuncSetAttribute(edge_mlp_mma, cudaFuncAttributeMaxDynamicSharedMemorySize, SMEM_ALLOC);

    prep_w_kernel<<<96, 256>>>(W1, W2);
    prep_node_kernel<<<(NODES * 64 + 255) / 256, 256>>>(node_attr);
    edge_mlp_mma<<<GRID, NT, SMEM_ALLOC>>>(node_attr, eidx, edge_attr,
                                           b1, b2, gamma_, beta_, (float*)d_out);
}

// round 17
// speedup vs baseline: 1.3100x; 1.0191x over previous
#include <cuda_runtime.h>
#include <cstdint>

#define EDGES  625000
#define NODES  50000
#define DD     128
#define BE     128
#define NT     512
#define NCTA   ((EDGES + BE - 1) / BE)   // 4883
#define GRID   152                       // persistent: 1 CTA per SM

// ---------------- smem layout (bytes) ----------------
#define SM_A0   0
#define SM_A1   16384
#define SM_B    32768          // resident B: 32 slices x 16 nt x 256B = 131072
#define SM_H    163840         // 128 rows x 256B = 32768
#define SM_PART 196608         // 128 rows x 4 x float2 = 4096
#define SM_P    200704
#define P_B1    (SM_P + 0)
#define P_B2    (SM_P + 512)
#define P_G     (SM_P + 1024)
#define P_BT    (SM_P + 1536)
#define P_IDX   (SM_P + 2048)  // 2 buffers x (send 512B + recv 512B) = 2048
#define SMEM_ALLOC 204800

// weights in fp16 m16n8k16 B-fragment layout (verified R6+)
__device__ __align__(16) uint32_t g_W1F[24 * 16 * 64];
__device__ __align__(16) uint32_t g_W2F[8 * 16 * 64];
// node_attr pre-converted to fp16 (uint32 = fp16x2), natural row-major
__device__ __align__(16) uint32_t g_node16[NODES * 64];   // 12.8MB

__device__ __forceinline__ uint32_t packf16(float lo, float hi) {
    uint32_t u;
    asm("cvt.rn.f16x2.f32 %0, %1, %2;" : "=r"(u) : "f"(hi), "f"(lo));
    return u;
}

__global__ void prep_w_kernel(const float* __restrict__ W1,
                              const float* __restrict__ W2) {
    int i = blockIdx.x * 256 + threadIdx.x;
    if (i < 24 * 16 * 64) {
        int blk = i >> 6, w = i & 63;
        int lane = w >> 1, r = w & 1;
        int g = lane >> 2, t = lane & 3;
        int ks = blk >> 4, nt = blk & 15;
        int k = ks * 16 + r * 8 + t * 2;
        int n = nt * 8 + g;
        g_W1F[i] = packf16(W1[k * 128 + n], W1[(k + 1) * 128 + n]);
    }
    if (i < 8 * 16 * 64) {
        int blk = i >> 6, w = i & 63;
        int lane = w >> 1, r = w & 1;
        int g = lane >> 2, t = lane & 3;
        int ks = blk >> 4, nt = blk & 15;
        int k = ks * 16 + r * 8 + t * 2;
        int n = nt * 8 + g;
        g_W2F[i] = packf16(W2[k * 128 + n], W2[(k + 1) * 128 + n]);
    }
}

__global__ void prep_node_kernel(const float* __restrict__ node_attr) {
    int i = blockIdx.x * 256 + threadIdx.x;
    if (i < NODES * 64) {
        float2 v = *(const float2*)(node_attr + i * 2);
        g_node16[i] = packf16(v.x, v.y);
    }
}

__device__ __forceinline__ void mma_fp16(float& c0, float& c1, float& c2, float& c3,
                                         uint32_t a0, uint32_t a1, uint32_t a2, uint32_t a3,
                                         uint32_t b0, uint32_t b1) {
    asm volatile("mma.sync.aligned.m16n8k16.row.col.f32.f16.f16.f32 "
                 "{%0,%1,%2,%3}, {%4,%5,%6,%7}, {%8,%9}, {%0,%1,%2,%3};"
                 : "+f"(c0), "+f"(c1), "+f"(c2), "+f"(c3)
                 : "r"(a0), "r"(a1), "r"(a2), "r"(a3), "r"(b0), "r"(b1));
}

__device__ __forceinline__ void ldsm4(uint32_t& r0, uint32_t& r1, uint32_t& r2, uint32_t& r3,
                                      uint32_t addr) {
    asm volatile("ldmatrix.sync.aligned.m8n8.x4.shared.b16 {%0,%1,%2,%3}, [%4];"
                 : "=r"(r0), "=r"(r1), "=r"(r2), "=r"(r3) : "r"(addr));
}

__device__ __forceinline__ void cp16(uint32_t saddr, const void* gptr) {
    asm volatile("cp.async.cg.shared.global [%0], [%1], 16;"
                 :: "r"(saddr), "l"(gptr));
}
#define CP_COMMIT() asm volatile("cp.async.commit_group;" ::: "memory")
#define CP_WAIT(n)  asm volatile("cp.async.wait_group %0;" :: "n"(n) : "memory")
#define HBAR(h) asm volatile("bar.sync %0, 256;" :: "r"(1 + (h)) : "memory")

__global__ __launch_bounds__(NT, 1) void edge_mlp_mma(
    const float* __restrict__ node_attr,
    const void*  __restrict__ eidx_raw,
    const float* __restrict__ edge_attr,
    const float* __restrict__ b1g,
    const float* __restrict__ b2g,
    const float* __restrict__ gg,
    const float* __restrict__ btg,
    float* __restrict__ out)
{
    extern __shared__ char smem[];
    uint32_t smb;
    asm("{ .reg .u64 t; cvta.to.shared.u64 t, %1; cvt.u32.u64 %0, t; }"
        : "=r"(smb) : "l"(smem));

    const int tid   = threadIdx.x;
    const int wid   = tid >> 5;
    const int lane  = tid & 31;
    const int g     = lane >> 2;
    const int t     = lane & 3;
    const int wm    = wid >> 2;    // 0..3 (M quarter); halves: wm{0,1} | wm{2,3}
    const int wn    = wid & 3;     // 0..3 (N quarter, 32 cols)
    const int h     = tid >> 8;
    const int ht    = tid & 255;
    const int lrow7 = lane & 7;
    const int rowb  = wm * 32 + lrow7 + 8 * ((lane >> 3) & 1);
    const int grx   = (lane >> 4) & 1;

    // ---- one-time: fill resident B (128KB) ----
    #pragma unroll
    for (int it = 0; it < 16; it++) {
        int idx = tid + it * NT;
        const uint32_t* src = (idx < 6144) ? (g_W1F + idx * 4)
                                           : (g_W2F + (idx - 6144) * 4);
        cp16(smb + SM_B + idx * 16, src);
    }
    CP_COMMIT();

    if (tid < 128) {
        ((float*)(smem + P_B1))[tid] = b1g[tid];
        ((float*)(smem + P_B2))[tid] = b2g[tid];
        ((float*)(smem + P_G ))[tid] = gg[tid];
        ((float*)(smem + P_BT))[tid] = btg[tid];
    }
    const int* raw32 = (const int*)eidx_raw;
    bool is64 = true;
    #pragma unroll
    for (int i = 0; i < 16; i++) is64 &= (raw32[2 * i + 1] == 0);
    CP_WAIT(0);
    __syncthreads();   // B + params resident (only full barrier)

    const float* B1c = (const float*)(smem + P_B1);
    const float* B2c = (const float*)(smem + P_B2);
    const float* Gc  = (const float*)(smem + P_G);
    const float* Btc = (const float*)(smem + P_BT);
    const char*  nbase = (const char*)g_node16;

    // ---- prologue: indices + A(0) for first tile, into idx buf 0 ----
    int pbuf = 0;
    {
        const int e0p = blockIdx.x * BE;
        if (ht < 64) {
            int row = h * 64 + ht;
            int eg = e0p + row; if (eg >= EDGES) eg = EDGES - 1;
            int s, r;
            if (is64) { const long long* p = (const long long*)eidx_raw;
                        s = (int)p[eg]; r = (int)p[EDGES + eg]; }
            else      { s = raw32[eg]; r = raw32[EDGES + eg]; }
            ((int*)(smem + P_IDX))[row] = s;
            ((int*)(smem + P_IDX + 512))[row] = r;
        }
        HBAR(h);
        const int* sS = (const int*)(smem + P_IDX);
        #pragma unroll
        for (int it = 0; it < 2; it++) {
            int idx = ht + it * 256;
            int row = h * 64 + (idx >> 3), jc2 = idx & 7;
            const char* src = nbase + (size_t)sS[row] * 256 + jc2 * 16;
            cp16(smb + SM_A0 + row * 128 + ((jc2 ^ (row & 7)) << 4), src);
        }
        CP_COMMIT();
    }

    // =========================== persistent tile loop ===========================
    #pragma unroll 1
    for (int tile = blockIdx.x; tile < NCTA; tile += GRID) {
        const int e0 = tile * BE;
        const int* sSend = (const int*)(smem + P_IDX + pbuf * 1024);
        const int* sRecv = (const int*)(smem + P_IDX + pbuf * 1024 + 512);

        float4 prA[4];
        float acc[2][4][4];
        #pragma unroll
        for (int i = 0; i < 2; i++)
            #pragma unroll
            for (int j = 0; j < 4; j++)
                #pragma unroll
                for (int r = 0; r < 4; r++) acc[i][j][r] = 0.0f;

        // ---------------- GEMM1: 6 chunks of k=64 ----------------
        #pragma unroll 1
        for (int c = 0; c < 6; c++) {
            const uint32_t aoff = (c & 1) ? SM_A1 : SM_A0;
            if (c < 4) {
                CP_WAIT(0);            // A(c) cp.async landed
            } else {
                // scatter edge chunk A(c) from prA (fp32 -> fp16, swizzled)
                char* abuf = smem + aoff;
                #pragma unroll
                for (int it = 0; it < 4; it++) {
                    int idx = ht + it * 256;
                    int row = h * 64 + (idx >> 4), jc = idx & 15;
                    int sw = (jc >> 1) ^ (row & 7);
                    uint2 v;
                    v.x = packf16(prA[it].x, prA[it].y);
                    v.y = packf16(prA[it].z, prA[it].w);
                    *(uint2*)(abuf + row * 128 + sw * 16 + (jc & 1) * 8) = v;
                }
            }
            HBAR(h);     // half's A(c) visible; half's MMA(c-1) done

            if (c < 3) {
                // issue cp.async A(c+1): node chunk
                int cn = c + 1;
                const int* nd = (cn < 2) ? sSend : sRecv;
                int koff = (cn & 1) * 128;
                uint32_t dstb = smb + ((cn & 1) ? SM_A1 : SM_A0);
                #pragma unroll
                for (int it = 0; it < 2; it++) {
                    int idx = ht + it * 256;
                    int row = h * 64 + (idx >> 3), jc2 = idx & 7;
                    const char* src = nbase + (size_t)nd[row] * 256 + koff + jc2 * 16;
                    cp16(dstb + row * 128 + ((jc2 ^ (row & 7)) << 4), src);
                }
                CP_COMMIT();
            } else if (c < 5) {
                // LDG prefetch edge chunk A(c+1)
                int cn = c + 1;
                #pragma unroll
                for (int it = 0; it < 4; it++) {
                    int idx = ht + it * 256;
                    int row = h * 64 + (idx >> 4), jc = idx & 15;
                    int eg = e0 + row; if (eg >= EDGES) eg = EDGES - 1;
                    prA[it] = *(const float4*)(edge_attr + (size_t)eg * DD +
                                               (cn - 4) * 64 + jc * 4);
                }
            }

            const char* bb = smem + SM_B;
            const uint32_t abase = smb + aoff;
            #pragma unroll
            for (int s = 0; s < 4; s++) {
                uint2 b[4];
                #pragma unroll
                for (int j = 0; j < 4; j++)
                    b[j] = *(const uint2*)(bb + (((c * 4 + s) * 16) + wn * 4 + j) * 256 + lane * 8);
                #pragma unroll
                for (int i = 0; i < 2; i++) {
                    uint32_t a0, a1, a2, a3;
                    uint32_t ad = abase + (rowb + i * 16) * 128 +
                                  (((s * 2 + grx) ^ lrow7) << 4);
                    ldsm4(a0, a1, a2, a3, ad);
                    #pragma unroll
                    for (int j = 0; j < 4; j++)
                        mma_fp16(acc[i][j][0], acc[i][j][1], acc[i][j][2], acc[i][j][3],
                                 a0, a1, a2, a3, b[j].x, b[j].y);
                }
            }
        }

        // ---------- epilogue1: bias + ReLU -> H (own half rows) ----------
        #pragma unroll
        for (int i = 0; i < 2; i++) {
            int row_lo = wm * 32 + i * 16 + g;
            #pragma unroll
            for (int j = 0; j < 4; j++) {
                int col = wn * 32 + j * 8 + 2 * t;
                float x0 = fmaxf(acc[i][j][0] + B1c[col],     0.0f);
                float x1 = fmaxf(acc[i][j][1] + B1c[col + 1], 0.0f);
                float x2 = fmaxf(acc[i][j][2] + B1c[col],     0.0f);
                float x3 = fmaxf(acc[i][j][3] + B1c[col + 1], 0.0f);
                int swg = ((wn * 4 + j) ^ g) * 16 + 4 * t;
                *(uint32_t*)(smem + SM_H + row_lo * 256 + swg)       = packf16(x0, x1);
                *(uint32_t*)(smem + SM_H + (row_lo + 8) * 256 + swg) = packf16(x2, x3);
                acc[i][j][0] = 0.0f; acc[i][j][1] = 0.0f;
                acc[i][j][2] = 0.0f; acc[i][j][3] = 0.0f;
            }
        }
        HBAR(h);       // half's H rows visible; A0's last reader (MMA 4) long done

        // ---------- prepare NEXT tile: indices + A(0) issue (GEMM2 shadow) ----------
        {
            int ntile = tile + GRID;
            if (ntile < NCTA) {
                int pn = pbuf ^ 1;
                const int e0n = ntile * BE;
                if (ht < 64) {
                    int row = h * 64 + ht;
                    int eg = e0n + row; if (eg >= EDGES) eg = EDGES - 1;
                    int s, r;
                    if (is64) { const long long* p = (const long long*)eidx_raw;
                                s = (int)p[eg]; r = (int)p[EDGES + eg]; }
                    else      { s = raw32[eg]; r = raw32[EDGES + eg]; }
                    ((int*)(smem + P_IDX + pn * 1024))[row] = s;
                    ((int*)(smem + P_IDX + pn * 1024 + 512))[row] = r;
                }
                HBAR(h);   // half's next indices visible
                const int* sSn = (const int*)(smem + P_IDX + pn * 1024);
                #pragma unroll
                for (int it = 0; it < 2; it++) {
                    int idx = ht + it * 256;
                    int row = h * 64 + (idx >> 3), jc2 = idx & 7;
                    const char* src = nbase + (size_t)sSn[row] * 256 + jc2 * 16;
                    cp16(smb + SM_A0 + row * 128 + ((jc2 ^ (row & 7)) << 4), src);
                }
                CP_COMMIT();
            }
        }

        // ---- GEMM2: 2 chunks, A via LDSM from H, B resident (ks 24..31) ----
        #pragma unroll
        for (int c2 = 0; c2 < 2; c2++) {
            const char* bb = smem + SM_B;
            #pragma unroll
            for (int s = 0; s < 4; s++) {
                uint2 b[4];
                #pragma unroll
                for (int j = 0; j < 4; j++)
                    b[j] = *(const uint2*)(bb + (((24 + c2 * 4 + s) * 16) + wn * 4 + j) * 256 + lane * 8);
                #pragma unroll
                for (int i = 0; i < 2; i++) {
                    uint32_t a0, a1, a2, a3;
                    uint32_t ad = smb + SM_H + (rowb + i * 16) * 256 +
                                  (((c2 * 8 + s * 2 + grx) ^ lrow7) << 4);
                    ldsm4(a0, a1, a2, a3, ad);
                    #pragma unroll
                    for (int j = 0; j < 4; j++)
                        mma_fp16(acc[i][j][0], acc[i][j][1], acc[i][j][2], acc[i][j][3],
                                 a0, a1, a2, a3, b[j].x, b[j].y);
                }
            }
        }

        // ---------- bias2 + LayerNorm from registers (own half rows) ----------
        {
            #pragma unroll
            for (int i = 0; i < 2; i++)
                #pragma unroll
                for (int j = 0; j < 4; j++) {
                    int col = wn * 32 + j * 8 + 2 * t;
                    acc[i][j][0] += B2c[col];     acc[i][j][1] += B2c[col + 1];
                    acc[i][j][2] += B2c[col];     acc[i][j][3] += B2c[col + 1];
                }
            float2* part = (float2*)(smem + SM_PART);   // [row][wn]
            #pragma unroll
            for (int i = 0; i < 2; i++)
                #pragma unroll
                for (int hi = 0; hi < 2; hi++) {
                    float s = 0.0f, q = 0.0f;
                    #pragma unroll
                    for (int j = 0; j < 4; j++) {
                        float v0 = acc[i][j][hi * 2], v1 = acc[i][j][hi * 2 + 1];
                        s += v0 + v1; q += v0 * v0 + v1 * v1;
                    }
                    s += __shfl_xor_sync(0xffffffffu, s, 1);
                    q += __shfl_xor_sync(0xffffffffu, q, 1);
                    s += __shfl_xor_sync(0xffffffffu, s, 2);
                    q += __shfl_xor_sync(0xffffffffu, q, 2);
                    if (t == 0) {
                        int row = wm * 32 + i * 16 + g + 8 * hi;
                        part[row * 4 + wn] = make_float2(s, q);
                    }
                }
        }
        HBAR(h);       // half's partials visible

        {
            const float2* part = (const float2*)(smem + SM_PART);
            #pragma unroll
            for (int i = 0; i < 2; i++)
                #pragma unroll
                for (int hi = 0; hi < 2; hi++) {
                    int row = wm * 32 + i * 16 + g + 8 * hi;
                    float2 p0 = part[row * 4 + 0], p1 = part[row * 4 + 1];
                    float2 p2 = part[row * 4 + 2], p3 = part[row * 4 + 3];
                    float sum = p0.x + p1.x + p2.x + p3.x;
                    float sq  = p0.y + p1.y + p2.y + p3.y;
                    float mu  = sum * (1.0f / 128.0f);
                    float var = sq * (1.0f / 128.0f) - mu * mu;
                    float rs  = rsqrtf(var + 1e-5f);
                    int eg = e0 + row;
                    if (eg < EDGES) {
                        float* o = out + (size_t)eg * DD;
                        #pragma unroll
                        for (int j = 0; j < 4; j++) {
                            int col = wn * 32 + j * 8 + 2 * t;
                            float2 v;
                            v.x = (acc[i][j][hi * 2]     - mu) * rs * Gc[col]     + Btc[col];
                            v.y = (acc[i][j][hi * 2 + 1] - mu) * rs * Gc[col + 1] + Btc[col + 1];
                            *(float2*)(o + col) = v;
                        }
                    }
                }
        }
        HBAR(h);       // tile done (part reads complete) before next tile reuses buffers
        pbuf ^= 1;
    }
}

extern "C" void kernel_launch(void* const* d_in, const int* in_sizes, int n_in,
                              void* d_out, int out_size) {
    const float* node_attr = (const float*)d_in[0];
    const void*  eidx      = d_in[1];
    const float* edge_attr = (const float*)d_in[2];
    const float* W1        = (const float*)d_in[3];
    const float* b1        = (const float*)d_in[4];
    const float* W2        = (const float*)d_in[5];
    const float* b2        = (const float*)d_in[6];
    const float* gamma_    = (const float*)d_in[7];
    const float* beta_     = (const float*)d_in[8];

    cudaFuncSetAttribute(edge_mlp_mma, cudaFuncAttributeMaxDynamicSharedMemorySize, SMEM_ALLOC);

    prep_w_kernel<<<96, 256>>>(W1, W2);
    prep_node_kernel<<<(NODES * 64 + 255) / 256, 256>>>(node_attr);
    edge_mlp_mma<<<GRID, NT, SMEM_ALLOC>>>(node_attr, eidx, edge_attr,
                                           b1, b2, gamma_, beta_, (float*)d_out);
}